// round 4
// baseline (speedup 1.0000x reference)
#include <cuda_runtime.h>
#include <cuda_bf16.h>

// out[b,i,o] = relu( sum_f s[b,i,f] * W[f,o] + bias[o] * deg[b,i] )
// where s[b,i,f] = sum_j adj[b,i,j] * concat(sf1,sf2)[b,i,j,f]
//       deg[b,i] = sum_j adj[b,i,j]
//
// Round 4: TWO rows per block (grid 1024 x 256 threads).
// Warps 0-3 own row 0, warps 4-7 own row 1 for every phase.

#define MJ   128      // neighbor count (j)
#define FE   64       // features per input tensor
#define FC   128      // concatenated features
#define FO   128      // output features

__global__ __launch_bounds__(256, 6)
void gcn_fused_kernel(const float* __restrict__ sf1,
                      const float* __restrict__ sf2,
                      const float* __restrict__ adj,
                      const float* __restrict__ W,
                      const float* __restrict__ bias,
                      float* __restrict__ out)
{
    __shared__ float2 s_comp[2][MJ];   // per-row compacted (adj value, j bits)
    __shared__ int    s_cnt[8];
    __shared__ float  s_dsum[8];
    __shared__ int    s_woff[8];       // row-local exclusive warp offsets
    __shared__ int    s_nnz[2];
    __shared__ float  s_deg[2];
    __shared__ float  s_sm[2][FC];
    __shared__ float4 red4[256];

    float* redf = reinterpret_cast<float*>(red4);

    const int row0 = blockIdx.x * 2;
    const int t    = threadIdx.x;
    const int w    = t >> 5;
    const int lane = t & 31;

    // ---- Phase 1: both adj rows -> registers, ballot metadata ----
    // warps 0-3 cover row 0's 128 j's, warps 4-7 cover row 1's.
    const int r1  = t >> 7;            // adj row this thread loads
    const int jt  = t & 127;
    const float a = __ldg(adj + (size_t)(row0 + r1) * MJ + jt);
    const unsigned bal = __ballot_sync(0xffffffffu, a != 0.0f);
    {
        float d = a;
        #pragma unroll
        for (int off = 16; off > 0; off >>= 1)
            d += __shfl_down_sync(0xffffffffu, d, off);
        if (lane == 0) { s_cnt[w] = __popc(bal); s_dsum[w] = d; }
    }
    __syncthreads();

    if (t < 2) {       // per-row prefix over its 4 warp counts
        const int b = t * 4;
        const int c0 = s_cnt[b], c1 = s_cnt[b+1], c2 = s_cnt[b+2], c3 = s_cnt[b+3];
        s_woff[b]   = 0;
        s_woff[b+1] = c0;
        s_woff[b+2] = c0 + c1;
        s_woff[b+3] = c0 + c1 + c2;
        s_nnz[t]    = c0 + c1 + c2 + c3;
        s_deg[t]    = s_dsum[b] + s_dsum[b+1] + s_dsum[b+2] + s_dsum[b+3];
    }
    __syncthreads();

    if (a != 0.0f) {
        const int pos = s_woff[w] + __popc(bal & ((1u << lane) - 1u));
        s_comp[r1][pos] = make_float2(a, __int_as_float(jt));
    }
    __syncthreads();

    // ---- Phase 2: gather. 4 warps per row, stride-4 entries, 4-deep MLP ----
    // Within a warp: lanes 0-15 load the 64-float sf1 row (float4 each),
    // lanes 16-31 load sf2. Channel quad = lane*4 (0..127 over half-warps).
    {
        const int r  = w >> 2;         // row this warp gathers
        const int wq = w & 3;          // entry-slice within row
        const int nnz = s_nnz[r];
        const float* base = ((lane < 16) ? sf1 : sf2)
                          + (size_t)(row0 + r) * MJ * FE + (lane & 15) * 4;
        const float2* comp = s_comp[r];
        float4 acc = make_float4(0.f, 0.f, 0.f, 0.f);
        int k = wq;
        for (; k + 12 < nnz; k += 16) {   // 4 independent 16B loads in flight
            const float2 e0 = comp[k];
            const float2 e1 = comp[k + 4];
            const float2 e2 = comp[k + 8];
            const float2 e3 = comp[k + 12];
            const float4 v0 = __ldcs(reinterpret_cast<const float4*>(
                                  base + (size_t)__float_as_int(e0.y) * FE));
            const float4 v1 = __ldcs(reinterpret_cast<const float4*>(
                                  base + (size_t)__float_as_int(e1.y) * FE));
            const float4 v2 = __ldcs(reinterpret_cast<const float4*>(
                                  base + (size_t)__float_as_int(e2.y) * FE));
            const float4 v3 = __ldcs(reinterpret_cast<const float4*>(
                                  base + (size_t)__float_as_int(e3.y) * FE));
            acc.x += e0.x * v0.x; acc.y += e0.x * v0.y;
            acc.z += e0.x * v0.z; acc.w += e0.x * v0.w;
            acc.x += e1.x * v1.x; acc.y += e1.x * v1.y;
            acc.z += e1.x * v1.z; acc.w += e1.x * v1.w;
            acc.x += e2.x * v2.x; acc.y += e2.x * v2.y;
            acc.z += e2.x * v2.z; acc.w += e2.x * v2.w;
            acc.x += e3.x * v3.x; acc.y += e3.x * v3.y;
            acc.z += e3.x * v3.z; acc.w += e3.x * v3.w;
        }
        for (; k < nnz; k += 4) {
            const float2 e = comp[k];
            const float4 v = __ldcs(reinterpret_cast<const float4*>(
                                 base + (size_t)__float_as_int(e.y) * FE));
            acc.x += e.x * v.x; acc.y += e.x * v.y;
            acc.z += e.x * v.z; acc.w += e.x * v.w;
        }
        red4[t] = acc;   // redf[w*128 + lane*4 + c] = partial(row w>>2, slice w&3)
    }
    __syncthreads();

    // combine 4 slice-partials per (row, channel)
    {
        const int r = t >> 7;          // row
        const int c = t & 127;         // channel
        float s = 0.0f;
        #pragma unroll
        for (int wq = 0; wq < 4; ++wq)
            s += redf[(r * 4 + wq) * FC + c];
        s_sm[r][c] = s;
    }
    __syncthreads();

    // ---- Phase 3: per row, s (1x128) @ W (128x128), split-K over 4 warps ----
    {
        const int r  = w >> 2;
        const int kq = w & 3;          // 32 f-values per slice
        const int oq = lane;           // 4 outputs via float4
        const float4* W4 = reinterpret_cast<const float4*>(W);
        float4 acc = make_float4(0.f, 0.f, 0.f, 0.f);
        const int f0 = kq * 32;
        #pragma unroll
        for (int k = 0; k < 32; ++k) {
            const int f = f0 + k;
            const float s  = s_sm[r][f];        // warp-broadcast LDS
            const float4 wv = W4[f * 32 + oq];  // coalesced, L1/L2-resident
            acc.x += s * wv.x;
            acc.y += s * wv.y;
            acc.z += s * wv.z;
            acc.w += s * wv.w;
        }
        red4[t] = acc;
    }
    __syncthreads();

    // ---- Final combine + bias*deg + relu + store (both rows) ----
    if (t < 64) {
        const int r  = t >> 5;
        const int oq = t & 31;
        float4 rs = red4[(r * 4 + 0) * 32 + oq];
        #pragma unroll
        for (int kq = 1; kq < 4; ++kq) {
            const float4 q = red4[(r * 4 + kq) * 32 + oq];
            rs.x += q.x; rs.y += q.y; rs.z += q.z; rs.w += q.w;
        }
        const float4 bb = reinterpret_cast<const float4*>(bias)[oq];
        const float  d  = s_deg[r];
        float4 o4;
        o4.x = fmaxf(rs.x + bb.x * d, 0.0f);
        o4.y = fmaxf(rs.y + bb.y * d, 0.0f);
        o4.z = fmaxf(rs.z + bb.z * d, 0.0f);
        o4.w = fmaxf(rs.w + bb.w * d, 0.0f);
        reinterpret_cast<float4*>(out)[(size_t)(row0 + r) * 32 + oq] = o4;
    }
}

extern "C" void kernel_launch(void* const* d_in, const int* in_sizes, int n_in,
                              void* d_out, int out_size)
{
    const float* sf1  = (const float*)d_in[0];  // (16,128,128,64)
    const float* sf2  = (const float*)d_in[1];  // (16,128,128,64)
    const float* adj  = (const float*)d_in[2];  // (16,128,128)
    const float* W    = (const float*)d_in[3];  // (128,128)
    const float* bias = (const float*)d_in[4];  // (128,)
    float* out = (float*)d_out;                 // (16,128,128)

    gcn_fused_kernel<<<1024, 256>>>(sf1, sf2, adj, W, bias, out);
}

// round 5
// speedup vs baseline: 1.5593x; 1.5593x over previous
#include <cuda_runtime.h>
#include <cuda_bf16.h>

// out[b,i,o] = relu( sum_f s[b,i,f] * W[f,o] + bias[o] * deg[b,i] )
// where s[b,i,f] = sum_j adj[b,i,j] * concat(sf1,sf2)[b,i,j,f]
//       deg[b,i] = sum_j adj[b,i,j]
//
// Round 5: 8 rows per block (grid 256 x 256 threads).
// Each WARP fully owns one row: adj load -> in-warp compaction -> gather
// (8-deep MLP) -> s vector to smem. Only 2 block barriers total.
// GEMM phase: each W float4 read is reused across 4 rows (register blocking),
// cutting weight L1 traffic 4x vs one-row-per-read.

#define RPB  8        // rows per block
#define MJ   128      // neighbor count (j)
#define FE   64       // features per input tensor
#define FC   128      // concatenated features
#define FO   128      // output features

__global__ __launch_bounds__(256, 4)
void gcn_fused_kernel(const float* __restrict__ sf1,
                      const float* __restrict__ sf2,
                      const float* __restrict__ adj,
                      const float* __restrict__ W,
                      const float* __restrict__ bias,
                      float* __restrict__ out)
{
    __shared__ int    s_off[RPB][MJ];        // compacted element offsets (j*FE)
    __shared__ float  s_val[RPB][MJ];        // compacted adjacency values
    __shared__ float  s_sm[RPB][FC];         // per-row aggregated features
    __shared__ float4 red4[RPB][4][32];      // GEMM partials [warp][row-in-grp][quad]
    __shared__ float  s_deg[RPB];

    const int row0 = blockIdx.x * RPB;
    const int t    = threadIdx.x;
    const int w    = t >> 5;                 // warp == row within block
    const int lane = t & 31;
    const int row  = row0 + w;

    // ---- Phase 1 (warp-local, no barriers): adj row -> compact ----
    const float* arow = adj + (size_t)row * MJ;
    const float a0 = __ldg(arow + lane);
    const float a1 = __ldg(arow + lane + 32);
    const float a2 = __ldg(arow + lane + 64);
    const float a3 = __ldg(arow + lane + 96);

    const unsigned b0 = __ballot_sync(0xffffffffu, a0 != 0.0f);
    const unsigned b1 = __ballot_sync(0xffffffffu, a1 != 0.0f);
    const unsigned b2 = __ballot_sync(0xffffffffu, a2 != 0.0f);
    const unsigned b3 = __ballot_sync(0xffffffffu, a3 != 0.0f);

    const int c0 = __popc(b0);
    const int c1 = __popc(b1);
    const int c2 = __popc(b2);
    const int nnz = c0 + c1 + c2 + __popc(b3);

    const unsigned lm = (1u << lane) - 1u;
    if (a0 != 0.0f) { const int p = __popc(b0 & lm);
                      s_off[w][p] = (lane      ) * FE; s_val[w][p] = a0; }
    if (a1 != 0.0f) { const int p = c0 + __popc(b1 & lm);
                      s_off[w][p] = (lane + 32 ) * FE; s_val[w][p] = a1; }
    if (a2 != 0.0f) { const int p = c0 + c1 + __popc(b2 & lm);
                      s_off[w][p] = (lane + 64 ) * FE; s_val[w][p] = a2; }
    if (a3 != 0.0f) { const int p = c0 + c1 + c2 + __popc(b3 & lm);
                      s_off[w][p] = (lane + 96 ) * FE; s_val[w][p] = a3; }

    {   // degree: warp reduce of a0+a1+a2+a3
        float d = (a0 + a1) + (a2 + a3);
        #pragma unroll
        for (int off = 16; off > 0; off >>= 1)
            d += __shfl_down_sync(0xffffffffu, d, off);
        if (lane == 0) s_deg[w] = d;
    }
    __syncwarp();   // s_off/s_val visible to the whole warp

    // ---- Phase 2 (warp-local): gather with 8 loads in flight ----
    // lanes 0-15 cover sf1 (channels 0..63), lanes 16-31 cover sf2 (64..127);
    // each lane owns channel quad lane*4..lane*4+3.
    {
        const float* base = ((lane < 16) ? sf1 : sf2)
                          + (size_t)row * MJ * FE + (lane & 15) * 4;
        float4 acc0 = make_float4(0.f, 0.f, 0.f, 0.f);
        float4 acc1 = make_float4(0.f, 0.f, 0.f, 0.f);
        int k = 0;
        for (; k + 7 < nnz; k += 8) {
            const int o0 = s_off[w][k    ], o1 = s_off[w][k + 1];
            const int o2 = s_off[w][k + 2], o3 = s_off[w][k + 3];
            const int o4 = s_off[w][k + 4], o5 = s_off[w][k + 5];
            const int o6 = s_off[w][k + 6], o7 = s_off[w][k + 7];
            const float4 v0 = __ldcs(reinterpret_cast<const float4*>(base + o0));
            const float4 v1 = __ldcs(reinterpret_cast<const float4*>(base + o1));
            const float4 v2 = __ldcs(reinterpret_cast<const float4*>(base + o2));
            const float4 v3 = __ldcs(reinterpret_cast<const float4*>(base + o3));
            const float4 v4 = __ldcs(reinterpret_cast<const float4*>(base + o4));
            const float4 v5 = __ldcs(reinterpret_cast<const float4*>(base + o5));
            const float4 v6 = __ldcs(reinterpret_cast<const float4*>(base + o6));
            const float4 v7 = __ldcs(reinterpret_cast<const float4*>(base + o7));
            const float q0 = s_val[w][k    ], q1 = s_val[w][k + 1];
            const float q2 = s_val[w][k + 2], q3 = s_val[w][k + 3];
            const float q4 = s_val[w][k + 4], q5 = s_val[w][k + 5];
            const float q6 = s_val[w][k + 6], q7 = s_val[w][k + 7];
            acc0.x += q0 * v0.x; acc0.y += q0 * v0.y; acc0.z += q0 * v0.z; acc0.w += q0 * v0.w;
            acc1.x += q1 * v1.x; acc1.y += q1 * v1.y; acc1.z += q1 * v1.z; acc1.w += q1 * v1.w;
            acc0.x += q2 * v2.x; acc0.y += q2 * v2.y; acc0.z += q2 * v2.z; acc0.w += q2 * v2.w;
            acc1.x += q3 * v3.x; acc1.y += q3 * v3.y; acc1.z += q3 * v3.z; acc1.w += q3 * v3.w;
            acc0.x += q4 * v4.x; acc0.y += q4 * v4.y; acc0.z += q4 * v4.z; acc0.w += q4 * v4.w;
            acc1.x += q5 * v5.x; acc1.y += q5 * v5.y; acc1.z += q5 * v5.z; acc1.w += q5 * v5.w;
            acc0.x += q6 * v6.x; acc0.y += q6 * v6.y; acc0.z += q6 * v6.z; acc0.w += q6 * v6.w;
            acc1.x += q7 * v7.x; acc1.y += q7 * v7.y; acc1.z += q7 * v7.z; acc1.w += q7 * v7.w;
        }
        for (; k < nnz; ++k) {
            const int   o = s_off[w][k];
            const float q = s_val[w][k];
            const float4 v = __ldcs(reinterpret_cast<const float4*>(base + o));
            acc0.x += q * v.x; acc0.y += q * v.y;
            acc0.z += q * v.z; acc0.w += q * v.w;
        }
        float4 s4;
        s4.x = acc0.x + acc1.x; s4.y = acc0.y + acc1.y;
        s4.z = acc0.z + acc1.z; s4.w = acc0.w + acc1.w;
        reinterpret_cast<float4*>(s_sm[w])[lane] = s4;
    }
    __syncthreads();

    // ---- Phase 3: GEMM with 4-row register blocking ----
    // warp w: row group g = w>>2 (rows g*4..g*4+3), f-slice (w&3)*32.
    // Each W float4 read serves 4 rows.
    {
        const int g  = w >> 2;
        const int f0 = (w & 3) * 32;
        const float4* W4 = reinterpret_cast<const float4*>(W);
        float4 a0 = make_float4(0.f, 0.f, 0.f, 0.f);
        float4 a1 = make_float4(0.f, 0.f, 0.f, 0.f);
        float4 a2 = make_float4(0.f, 0.f, 0.f, 0.f);
        float4 a3 = make_float4(0.f, 0.f, 0.f, 0.f);
        #pragma unroll 8
        for (int k = 0; k < 32; ++k) {
            const int f = f0 + k;
            const float4 wv = W4[f * 32 + lane];    // L1/L2-resident, coalesced
            const float s0 = s_sm[g * 4 + 0][f];    // broadcast LDS
            const float s1 = s_sm[g * 4 + 1][f];
            const float s2 = s_sm[g * 4 + 2][f];
            const float s3 = s_sm[g * 4 + 3][f];
            a0.x += s0 * wv.x; a0.y += s0 * wv.y; a0.z += s0 * wv.z; a0.w += s0 * wv.w;
            a1.x += s1 * wv.x; a1.y += s1 * wv.y; a1.z += s1 * wv.z; a1.w += s1 * wv.w;
            a2.x += s2 * wv.x; a2.y += s2 * wv.y; a2.z += s2 * wv.z; a2.w += s2 * wv.w;
            a3.x += s3 * wv.x; a3.y += s3 * wv.y; a3.z += s3 * wv.z; a3.w += s3 * wv.w;
        }
        red4[w][0][lane] = a0;
        red4[w][1][lane] = a1;
        red4[w][2][lane] = a2;
        red4[w][3][lane] = a3;
    }
    __syncthreads();

    // ---- Phase 4: combine 4 f-slices + bias*deg + relu + store ----
    // thread t -> (g = t>>7, r = (t>>5)&3, q = t&31): one float4 of output.
    {
        const int g = t >> 7;
        const int r = (t >> 5) & 3;
        const int q = t & 31;
        float4 rs = red4[g * 4 + 0][r][q];
        #pragma unroll
        for (int sl = 1; sl < 4; ++sl) {
            const float4 p = red4[g * 4 + sl][r][q];
            rs.x += p.x; rs.y += p.y; rs.z += p.z; rs.w += p.w;
        }
        const float4 bb = reinterpret_cast<const float4*>(bias)[q];
        const float  d  = s_deg[g * 4 + r];
        float4 o4;
        o4.x = fmaxf(rs.x + bb.x * d, 0.0f);
        o4.y = fmaxf(rs.y + bb.y * d, 0.0f);
        o4.z = fmaxf(rs.z + bb.z * d, 0.0f);
        o4.w = fmaxf(rs.w + bb.w * d, 0.0f);
        reinterpret_cast<float4*>(out)[(size_t)(row0 + g * 4 + r) * 32 + q] = o4;
    }
}

extern "C" void kernel_launch(void* const* d_in, const int* in_sizes, int n_in,
                              void* d_out, int out_size)
{
    const float* sf1  = (const float*)d_in[0];  // (16,128,128,64)
    const float* sf2  = (const float*)d_in[1];  // (16,128,128,64)
    const float* adj  = (const float*)d_in[2];  // (16,128,128)
    const float* W    = (const float*)d_in[3];  // (128,128)
    const float* bias = (const float*)d_in[4];  // (128,)
    float* out = (float*)d_out;                 // (16,128,128)

    gcn_fused_kernel<<<2048 / RPB, 256>>>(sf1, sf2, adj, W, bias, out);
}